// round 10
// baseline (speedup 1.0000x reference)
#include <cuda_runtime.h>

// Fused 2-layer LSTM + FC decoder — 512-thread K-split edition.
// x:[4096,256,16] -> LSTM(16->64) -> LSTM(64->1) -> FC(1->1) -> out:[4096,256,1]
//
// block = NB(16) batches, 512 threads, grid 256, 2 blocks/SM (occ ~50%).
// Thread (g = tid&255, half = tid>>8) owns HALF of gate g's dot: 32 h-weights
// + 8 x-weights in registers (packed f32x2). Phase 1: 16 half-dots (20 fma2
// each), partial -> smem. Phase 2: combine halves + bias, activate, update
// c/h (2 cells/thread). No shuffles in the dot path. Layer 2 (H=1)+FC:
// warp w -> batch w (16 warps, 1 chain each), deferred 1 step, overlapped.

#define T_STEPS 256
#define IN_DIM  16
#define H1      64
#define G1      256   // 4*H1
#define NB      16
#define THREADS 512

typedef unsigned long long ull;

__device__ __forceinline__ ull fma2(ull a, ull b, ull c) {
    ull d;
    asm("fma.rn.f32x2 %0, %1, %2, %3;" : "=l"(d) : "l"(a), "l"(b), "l"(c));
    return d;
}
__device__ __forceinline__ float2 u2f(ull v) {
    float2 r;
    asm("mov.b64 {%0, %1}, %2;" : "=f"(r.x), "=f"(r.y) : "l"(v));
    return r;
}

__device__ __forceinline__ float sigmoid_f(float x) {
    return __fdividef(1.0f, 1.0f + __expf(-x));
}
__device__ __forceinline__ float tanh_f(float x) {
    return __fdividef(2.0f, 1.0f + __expf(-2.0f * x)) - 1.0f;
}

// One LSTM2 (H=1) step + FC for one batch element, done by one warp.
// w_ih2 row via LDG each step (L1-hit) to save registers.
__device__ __forceinline__ void layer2_step(const float* __restrict__ hb,
                                            const float* __restrict__ w2p,
                                            float bias2, float whh2,
                                            float fcw, float fcb,
                                            float& h2, float& c2,
                                            float* __restrict__ outp, int lane)
{
    float part = 0.0f;
    #pragma unroll
    for (int m = 0; m < 8; m++) part = fmaf(w2p[m], hb[m], part);
    part += __shfl_down_sync(0xffffffffu, part, 4);
    part += __shfl_down_sync(0xffffffffu, part, 2);
    part += __shfl_down_sync(0xffffffffu, part, 1);
    float gate = fmaf(whh2, h2, part + bias2);   // valid where (lane&7)==0
    float gi = __shfl_sync(0xffffffffu, gate, 0);
    float gf = __shfl_sync(0xffffffffu, gate, 8);
    float gg = __shfl_sync(0xffffffffu, gate, 16);
    float go = __shfl_sync(0xffffffffu, gate, 24);
    float ii = sigmoid_f(gi);
    float ff = sigmoid_f(gf);
    float g2 = tanh_f(gg);
    float oo = sigmoid_f(go);
    c2 = fmaf(ff, c2, ii * g2);
    h2 = oo * tanh_f(c2);
    if (lane == 0) *outp = fmaf(h2, fcw, fcb);
}

__global__ __launch_bounds__(THREADS, 2)
void lstm_fused_kernel(const float* __restrict__ x,
                       const float* __restrict__ w_ih1, const float* __restrict__ w_hh1,
                       const float* __restrict__ b_ih1, const float* __restrict__ b_hh1,
                       const float* __restrict__ w_ih2, const float* __restrict__ w_hh2,
                       const float* __restrict__ b_ih2, const float* __restrict__ b_hh2,
                       const float* __restrict__ fc_w, const float* __restrict__ fc_b,
                       float* __restrict__ out)
{
    __shared__ __align__(16) float x_sh[NB * IN_DIM];      // 1 KB: staged x(t)
    __shared__ __align__(16) float h_sh[NB * H1];          // 4 KB: layer-1 hidden
    __shared__ float part_sh[2][NB][G1];                   // 32 KB: half-dot partials
    __shared__ float bias_sh[G1];                          // 1 KB: b_ih1+b_hh1

    const int tid  = threadIdx.x;
    const int b0   = blockIdx.x * NB;
    const int wid  = tid >> 5;
    const int lane = tid & 31;
    const int g    = tid & 255;   // gate id
    const int half = tid >> 8;    // K-half

    // ---- half weights in registers as packed f32x2 ----
    ull whh[16];   // 32 floats: w_hh1[g, half*32 .. +32)
    ull wih[4];    // 8 floats:  w_ih1[g, half*8 .. +8)
    {
        const ulonglong2* wr = (const ulonglong2*)(w_hh1 + g * H1 + half * 32);
        #pragma unroll
        for (int m = 0; m < 8; m++) { ulonglong2 v = wr[m]; whh[2*m] = v.x; whh[2*m+1] = v.y; }
        const ulonglong2* wi = (const ulonglong2*)(w_ih1 + g * IN_DIM + half * 8);
        #pragma unroll
        for (int m = 0; m < 2; m++) { ulonglong2 v = wi[m]; wih[2*m] = v.x; wih[2*m+1] = v.y; }
    }
    if (half == 0) bias_sh[g] = b_ih1[g] + b_hh1[g];

    // ---- layer-2 + FC per-warp setup: warp w -> batch w (16 warps) ----
    const int q  = lane >> 3;
    const int ch = lane & 7;
    const float* w2p  = w_ih2 + q * H1 + ch * 8;   // LDG per step (L1-hit)
    const float bias2 = b_ih2[q] + b_hh2[q];
    const float whh2  = w_hh2[q];
    const float fcw   = fc_w[0];
    const float fcb   = fc_b[0];

    // ---- states ----
    float c1[2] = {0.0f, 0.0f};   // cells: cell id = k*512 + tid
    float c2 = 0.0f, h2 = 0.0f;   // layer-2 (warp-uniform, warp = batch)
    if (tid < NB * H1) h_sh[tid] = 0.0f;
    if (512 + tid < NB * H1) h_sh[512 + tid] = 0.0f;

    const float* hb2 = h_sh + wid * H1 + ch * 8;
    float* outb = out + (b0 + wid) * T_STEPS;

    // x staging: threads 0..255 own (xnb = tid>>4, xi = tid&15)
    const bool xduty = (tid < NB * IN_DIM);
    const float* xsrc = x + ((b0 + (tid >> 4)) * T_STEPS) * IN_DIM + (tid & 15);
    if (xduty) x_sh[tid] = xsrc[0];
    __syncthreads();

    for (int t = 0; t < T_STEPS; t++) {
        // ---- phase 1: prefetch x(t+1); 16 half-dots; layer2(t-1) ----
        float xr = 0.0f;
        if (xduty && t + 1 < T_STEPS) xr = xsrc[(t + 1) * IN_DIM];

        #pragma unroll 4
        for (int nb = 0; nb < NB; nb++) {
            ull a0 = 0, a1 = 0;
            const ulonglong2* hv = (const ulonglong2*)(h_sh + nb * H1 + half * 32);
            #pragma unroll
            for (int m = 0; m < 8; m += 2) {
                ulonglong2 p = hv[m];
                ulonglong2 r = hv[m + 1];
                a0 = fma2(whh[2*m + 0], p.x, a0);
                a1 = fma2(whh[2*m + 1], p.y, a1);
                a0 = fma2(whh[2*m + 2], r.x, a0);
                a1 = fma2(whh[2*m + 3], r.y, a1);
            }
            {
                const ulonglong2* xv = (const ulonglong2*)(x_sh + nb * IN_DIM + half * 8);
                ulonglong2 p = xv[0];
                ulonglong2 r = xv[1];
                a0 = fma2(wih[0], p.x, a0);
                a1 = fma2(wih[1], p.y, a1);
                a0 = fma2(wih[2], r.x, a0);
                a1 = fma2(wih[3], r.y, a1);
            }
            float2 f0 = u2f(a0), f1 = u2f(a1);
            part_sh[half][nb][g] = (f0.x + f0.y) + (f1.x + f1.y);
        }

        // deferred layer-2 for t-1 (pure reader of h_sh = h1(t-1)); 1 batch/warp
        if (t > 0) {
            layer2_step(hb2, w2p, bias2, whh2, fcw, fcb, h2, c2, outb + (t - 1), lane);
        }
        __syncthreads();

        // ---- phase 2: combine halves, activate, update 2 cells; publish x ----
        #pragma unroll
        for (int k = 0; k < 2; k++) {
            const int cell = k * 512 + tid;          // 0..1023
            const int unb  = cell >> 6;              // batch 0..15
            const int uj   = cell & 63;              // hidden index
            float pi = (part_sh[0][unb][uj]           + part_sh[1][unb][uj])           + bias_sh[uj];
            float pf = (part_sh[0][unb][H1 + uj]      + part_sh[1][unb][H1 + uj])      + bias_sh[H1 + uj];
            float pg = (part_sh[0][unb][2 * H1 + uj]  + part_sh[1][unb][2 * H1 + uj])  + bias_sh[2 * H1 + uj];
            float po = (part_sh[0][unb][3 * H1 + uj]  + part_sh[1][unb][3 * H1 + uj])  + bias_sh[3 * H1 + uj];
            float gi = sigmoid_f(pi);
            float gf = sigmoid_f(pf);
            float gg = tanh_f(pg);
            float go = sigmoid_f(po);
            c1[k] = fmaf(gf, c1[k], gi * gg);
            h_sh[unb * H1 + uj] = go * tanh_f(c1[k]);
        }
        if (xduty) x_sh[tid] = xr;
        __syncthreads();   // h(t), x(t+1) published
    }

    // Tail: layer-2 + FC for the final timestep (h1(T-1))
    layer2_step(hb2, w2p, bias2, whh2, fcw, fcb, h2, c2, outb + (T_STEPS - 1), lane);
}

extern "C" void kernel_launch(void* const* d_in, const int* in_sizes, int n_in,
                              void* d_out, int out_size) {
    const int B = in_sizes[0] / (T_STEPS * IN_DIM);   // 4096
    lstm_fused_kernel<<<B / NB, THREADS>>>(
        (const float*)d_in[0],
        (const float*)d_in[1], (const float*)d_in[2],
        (const float*)d_in[3], (const float*)d_in[4],
        (const float*)d_in[5], (const float*)d_in[6],
        (const float*)d_in[7], (const float*)d_in[8],
        (const float*)d_in[9], (const float*)d_in[10],
        (float*)d_out);
}

// round 14
// speedup vs baseline: 1.2775x; 1.2775x over previous
#include <cuda_runtime.h>

// Fused 2-layer LSTM + FC decoder — NB=16 + MUFU.TANH activations.
// x:[4096,256,16] -> LSTM(16->64) -> LSTM(64->1) -> FC(1->1) -> out:[4096,256,1]
//
// block = NB(16) batch elements, 256 threads, grid 256 (~1 wave, 2 blocks/SM).
// Thread g owns gate g of layer 1; weight row in registers (packed f32x2);
// per step: 16 independent 80-MAC dots via fma.rn.f32x2. 2 syncthreads/step.
// Activations via hardware tanh.approx.f32 (sigmoid = 0.5+0.5*tanh(x/2)).
// x double-buffered through registers. Layer 2 (H=1)+FC deferred one step,
// 2 batches per warp on warps 0-7, pair-interleaved, overlapped with gates.

#define T_STEPS 256
#define IN_DIM  16
#define H1      64
#define G1      256   // 4*H1
#define NB      16
#define THREADS 256

typedef unsigned long long ull;

__device__ __forceinline__ ull fma2(ull a, ull b, ull c) {
    ull d;
    asm("fma.rn.f32x2 %0, %1, %2, %3;" : "=l"(d) : "l"(a), "l"(b), "l"(c));
    return d;
}
__device__ __forceinline__ float2 u2f(ull v) {
    float2 r;
    asm("mov.b64 {%0, %1}, %2;" : "=f"(r.x), "=f"(r.y) : "l"(v));
    return r;
}

__device__ __forceinline__ float tanh_f(float x) {
    float y;
    asm("tanh.approx.f32 %0, %1;" : "=f"(y) : "f"(x));
    return y;
}
__device__ __forceinline__ float sigmoid_f(float x) {
    return fmaf(0.5f, tanh_f(0.5f * x), 0.5f);
}

// LSTM2 (H=1) + FC for TWO batch elements, one warp, chains interleaved.
__device__ __forceinline__ void layer2_pair(const float* __restrict__ hb0,
                                            const float* __restrict__ hb1,
                                            const float w2[8], float bias2, float whh2,
                                            float fcw, float fcb,
                                            float& h2a, float& c2a,
                                            float& h2b, float& c2b,
                                            float* __restrict__ o0, float* __restrict__ o1,
                                            int lane)
{
    float p0 = 0.0f, p1 = 0.0f;
    #pragma unroll
    for (int m = 0; m < 8; m++) {
        p0 = fmaf(w2[m], hb0[m], p0);
        p1 = fmaf(w2[m], hb1[m], p1);
    }
    p0 += __shfl_down_sync(0xffffffffu, p0, 4);
    p1 += __shfl_down_sync(0xffffffffu, p1, 4);
    p0 += __shfl_down_sync(0xffffffffu, p0, 2);
    p1 += __shfl_down_sync(0xffffffffu, p1, 2);
    p0 += __shfl_down_sync(0xffffffffu, p0, 1);
    p1 += __shfl_down_sync(0xffffffffu, p1, 1);
    float ga = fmaf(whh2, h2a, p0 + bias2);   // valid where (lane&7)==0
    float gb = fmaf(whh2, h2b, p1 + bias2);
    float gi0 = __shfl_sync(0xffffffffu, ga, 0),  gi1 = __shfl_sync(0xffffffffu, gb, 0);
    float gf0 = __shfl_sync(0xffffffffu, ga, 8),  gf1 = __shfl_sync(0xffffffffu, gb, 8);
    float gg0 = __shfl_sync(0xffffffffu, ga, 16), gg1 = __shfl_sync(0xffffffffu, gb, 16);
    float go0 = __shfl_sync(0xffffffffu, ga, 24), go1 = __shfl_sync(0xffffffffu, gb, 24);
    float i0 = sigmoid_f(gi0), i1 = sigmoid_f(gi1);
    float f0 = sigmoid_f(gf0), f1 = sigmoid_f(gf1);
    float tg0 = tanh_f(gg0),   tg1 = tanh_f(gg1);
    float o0v = sigmoid_f(go0), o1v = sigmoid_f(go1);
    c2a = fmaf(f0, c2a, i0 * tg0);
    c2b = fmaf(f1, c2b, i1 * tg1);
    h2a = o0v * tanh_f(c2a);
    h2b = o1v * tanh_f(c2b);
    if (lane == 0) {
        *o0 = fmaf(h2a, fcw, fcb);
        *o1 = fmaf(h2b, fcw, fcb);
    }
}

__global__ __launch_bounds__(THREADS, 2)
void lstm_fused_kernel(const float* __restrict__ x,
                       const float* __restrict__ w_ih1, const float* __restrict__ w_hh1,
                       const float* __restrict__ b_ih1, const float* __restrict__ b_hh1,
                       const float* __restrict__ w_ih2, const float* __restrict__ w_hh2,
                       const float* __restrict__ b_ih2, const float* __restrict__ b_hh2,
                       const float* __restrict__ fc_w, const float* __restrict__ fc_b,
                       float* __restrict__ out)
{
    __shared__ __align__(16) float x_sh[NB * IN_DIM];   // 256: staged x(t)
    __shared__ __align__(16) float h_sh[NB * H1];       // 1024: layer-1 hidden
    __shared__ float gact[NB * G1];                      // 4096: activated gates

    const int tid  = threadIdx.x;
    const int b0   = blockIdx.x * NB;
    const int wid  = tid >> 5;
    const int lane = tid & 31;

    // ---- layer-1 weights in registers as packed f32x2 (thread = gate tid) ----
    ull whh[32];   // 64 floats
    ull wih[8];    // 16 floats
    {
        const ulonglong2* wr = (const ulonglong2*)(w_hh1 + tid * H1);
        #pragma unroll
        for (int m = 0; m < 16; m++) { ulonglong2 v = wr[m]; whh[2*m] = v.x; whh[2*m+1] = v.y; }
        const ulonglong2* wi = (const ulonglong2*)(w_ih1 + tid * IN_DIM);
        #pragma unroll
        for (int m = 0; m < 4; m++) { ulonglong2 v = wi[m]; wih[2*m] = v.x; wih[2*m+1] = v.y; }
    }
    const float bias1 = b_ih1[tid] + b_hh1[tid];

    // ---- layer-2 + FC per-warp setup: warp w -> batches 2w, 2w+1 ----
    const int q  = lane >> 3;
    const int ch = lane & 7;
    float w2[8];
    #pragma unroll
    for (int m = 0; m < 8; m++) w2[m] = w_ih2[q * H1 + ch * 8 + m];
    const float bias2 = b_ih2[q] + b_hh2[q];
    const float whh2  = w_hh2[q];
    const float fcw   = fc_w[0];
    const float fcb   = fc_b[0];

    // ---- states ----
    float c1[4];                 // 4 cells per thread: cell id = k*256 + tid
    #pragma unroll
    for (int k = 0; k < 4; k++) c1[k] = 0.0f;
    float c2[2] = {0.0f, 0.0f};  // layer-2 per-warp (2 batches)
    float h2[2] = {0.0f, 0.0f};
    #pragma unroll
    for (int k = 0; k < 4; k++) h_sh[k * 256 + tid] = 0.0f;

    const int cls = tid >> 6;    // 0:i 1:f 2:g 3:o
    const float* hb2a = h_sh + (wid * 2 + 0) * H1 + ch * 8;
    const float* hb2b = h_sh + (wid * 2 + 1) * H1 + ch * 8;
    float* outa = out + (b0 + wid * 2 + 0) * T_STEPS;
    float* outc = out + (b0 + wid * 2 + 1) * T_STEPS;

    // x staging: every thread owns (xnb = tid>>4, xi = tid&15)
    const float* xsrc = x + ((b0 + (tid >> 4)) * T_STEPS) * IN_DIM + (tid & 15);
    x_sh[tid] = xsrc[0];
    __syncthreads();

    for (int t = 0; t < T_STEPS; t++) {
        // ---- phase 1: prefetch x(t+1); gates(t) for 16 batches; layer2(t-1) ----
        float xr = 0.0f;
        if (t + 1 < T_STEPS) xr = xsrc[(t + 1) * IN_DIM];

        #pragma unroll 4
        for (int nb = 0; nb < NB; nb++) {
            ull a0 = 0, a1 = 0, a2 = 0, a3 = 0;
            const ulonglong2* hv = (const ulonglong2*)(h_sh + nb * H1);
            #pragma unroll
            for (int m = 0; m < 16; m += 2) {
                ulonglong2 p = hv[m];
                ulonglong2 r = hv[m + 1];
                a0 = fma2(whh[2*m + 0], p.x, a0);
                a1 = fma2(whh[2*m + 1], p.y, a1);
                a2 = fma2(whh[2*m + 2], r.x, a2);
                a3 = fma2(whh[2*m + 3], r.y, a3);
            }
            // full 16-float x projection (4 ulonglong2 loads, wih[0..7])
            const ulonglong2* xv = (const ulonglong2*)(x_sh + nb * IN_DIM);
            #pragma unroll
            for (int m = 0; m < 4; m += 2) {
                ulonglong2 p = xv[m];
                ulonglong2 r = xv[m + 1];
                a0 = fma2(wih[2*m + 0], p.x, a0);
                a1 = fma2(wih[2*m + 1], p.y, a1);
                a2 = fma2(wih[2*m + 2], r.x, a2);
                a3 = fma2(wih[2*m + 3], r.y, a3);
            }
            float2 f0 = u2f(a0), f1 = u2f(a1), f2 = u2f(a2), f3 = u2f(a3);
            float pre = ((f0.x + f0.y) + (f1.x + f1.y))
                      + ((f2.x + f2.y) + (f3.x + f3.y)) + bias1;
            gact[nb * G1 + tid] = (cls == 2) ? tanh_f(pre) : sigmoid_f(pre);
        }

        // deferred layer-2 for t-1 (pure reader of h_sh = h1(t-1)); 2 batches/warp
        if (t > 0) {
            layer2_pair(hb2a, hb2b, w2, bias2, whh2, fcw, fcb,
                        h2[0], c2[0], h2[1], c2[1], outa + (t - 1), outc + (t - 1), lane);
        }
        __syncthreads();

        // ---- phase 2: update 4 cells per thread; publish x(t+1) ----
        #pragma unroll
        for (int k = 0; k < 4; k++) {
            const int cell = k * 256 + tid;          // 0..1023
            const int unb  = cell >> 6;              // batch 0..15
            const int uj   = cell & 63;              // hidden index
            const float* gb = gact + unb * G1;
            float gi = gb[uj];
            float gf = gb[H1 + uj];
            float gg = gb[2 * H1 + uj];
            float go = gb[3 * H1 + uj];
            c1[k] = fmaf(gf, c1[k], gi * gg);
            h_sh[unb * H1 + uj] = go * tanh_f(c1[k]);
        }
        x_sh[tid] = xr;
        __syncthreads();   // h(t), x(t+1) published
    }

    // Tail: layer-2 + FC for the final timestep (h1(T-1))
    layer2_pair(hb2a, hb2b, w2, bias2, whh2, fcw, fcb,
                h2[0], c2[0], h2[1], c2[1],
                outa + (T_STEPS - 1), outc + (T_STEPS - 1), lane);
}

extern "C" void kernel_launch(void* const* d_in, const int* in_sizes, int n_in,
                              void* d_out, int out_size) {
    const int B = in_sizes[0] / (T_STEPS * IN_DIM);   // 4096
    lstm_fused_kernel<<<B / NB, THREADS>>>(
        (const float*)d_in[0],
        (const float*)d_in[1], (const float*)d_in[2],
        (const float*)d_in[3], (const float*)d_in[4],
        (const float*)d_in[5], (const float*)d_in[6],
        (const float*)d_in[7], (const float*)d_in[8],
        (const float*)d_in[9], (const float*)d_in[10],
        (float*)d_out);
}

// round 15
// speedup vs baseline: 1.4967x; 1.1716x over previous
#include <cuda_runtime.h>

// Fused 2-layer LSTM + FC decoder — gate-pair x K-half edition (LDS halved).
// x:[4096,256,16] -> LSTM(16->64) -> LSTM(64->1) -> FC(1->1) -> out:[4096,256,1]
//
// block = NB(16) batches, 256 threads, grid 256, 2 blocks/SM.
// Thread (p = tid&127, kh = tid>>7) owns gates {p, p+128} restricted to
// K-half kh: 80 weight regs (packed f32x2). Per nb: 10 LDS.128 (half h + half
// x) feed 40 fma2 (two half-dots) -> 2 fp32 partials to smem. Phase 2 combines
// halves + bias, activates (tanh.approx), updates c/h. Layer 2 (H=1)+FC:
// 2 batches/warp, pair-interleaved, deferred one step, overlapped with gates.

#define T_STEPS 256
#define IN_DIM  16
#define H1      64
#define G1      256   // 4*H1
#define NB      16
#define THREADS 256

typedef unsigned long long ull;

__device__ __forceinline__ ull fma2(ull a, ull b, ull c) {
    ull d;
    asm("fma.rn.f32x2 %0, %1, %2, %3;" : "=l"(d) : "l"(a), "l"(b), "l"(c));
    return d;
}
__device__ __forceinline__ float2 u2f(ull v) {
    float2 r;
    asm("mov.b64 {%0, %1}, %2;" : "=f"(r.x), "=f"(r.y) : "l"(v));
    return r;
}

__device__ __forceinline__ float tanh_f(float x) {
    float y;
    asm("tanh.approx.f32 %0, %1;" : "=f"(y) : "f"(x));
    return y;
}
__device__ __forceinline__ float sigmoid_f(float x) {
    return fmaf(0.5f, tanh_f(0.5f * x), 0.5f);
}

// LSTM2 (H=1) + FC for TWO batch elements, one warp, chains interleaved.
__device__ __forceinline__ void layer2_pair(const float* __restrict__ hb0,
                                            const float* __restrict__ hb1,
                                            const float w2[8], float bias2, float whh2,
                                            float fcw, float fcb,
                                            float& h2a, float& c2a,
                                            float& h2b, float& c2b,
                                            float* __restrict__ o0, float* __restrict__ o1,
                                            int lane)
{
    float p0 = 0.0f, p1 = 0.0f;
    #pragma unroll
    for (int m = 0; m < 8; m++) {
        p0 = fmaf(w2[m], hb0[m], p0);
        p1 = fmaf(w2[m], hb1[m], p1);
    }
    p0 += __shfl_down_sync(0xffffffffu, p0, 4);
    p1 += __shfl_down_sync(0xffffffffu, p1, 4);
    p0 += __shfl_down_sync(0xffffffffu, p0, 2);
    p1 += __shfl_down_sync(0xffffffffu, p1, 2);
    p0 += __shfl_down_sync(0xffffffffu, p0, 1);
    p1 += __shfl_down_sync(0xffffffffu, p1, 1);
    float ga = fmaf(whh2, h2a, p0 + bias2);   // valid where (lane&7)==0
    float gb = fmaf(whh2, h2b, p1 + bias2);
    float gi0 = __shfl_sync(0xffffffffu, ga, 0),  gi1 = __shfl_sync(0xffffffffu, gb, 0);
    float gf0 = __shfl_sync(0xffffffffu, ga, 8),  gf1 = __shfl_sync(0xffffffffu, gb, 8);
    float gg0 = __shfl_sync(0xffffffffu, ga, 16), gg1 = __shfl_sync(0xffffffffu, gb, 16);
    float go0 = __shfl_sync(0xffffffffu, ga, 24), go1 = __shfl_sync(0xffffffffu, gb, 24);
    float i0 = sigmoid_f(gi0), i1 = sigmoid_f(gi1);
    float f0 = sigmoid_f(gf0), f1 = sigmoid_f(gf1);
    float tg0 = tanh_f(gg0),   tg1 = tanh_f(gg1);
    float o0v = sigmoid_f(go0), o1v = sigmoid_f(go1);
    c2a = fmaf(f0, c2a, i0 * tg0);
    c2b = fmaf(f1, c2b, i1 * tg1);
    h2a = o0v * tanh_f(c2a);
    h2b = o1v * tanh_f(c2b);
    if (lane == 0) {
        *o0 = fmaf(h2a, fcw, fcb);
        *o1 = fmaf(h2b, fcw, fcb);
    }
}

__global__ __launch_bounds__(THREADS, 2)
void lstm_fused_kernel(const float* __restrict__ x,
                       const float* __restrict__ w_ih1, const float* __restrict__ w_hh1,
                       const float* __restrict__ b_ih1, const float* __restrict__ b_hh1,
                       const float* __restrict__ w_ih2, const float* __restrict__ w_hh2,
                       const float* __restrict__ b_ih2, const float* __restrict__ b_hh2,
                       const float* __restrict__ fc_w, const float* __restrict__ fc_b,
                       float* __restrict__ out)
{
    __shared__ __align__(16) float x_sh[NB * IN_DIM];   // 1 KB: staged x(t)
    __shared__ __align__(16) float h_sh[NB * H1];       // 4 KB: layer-1 hidden (fp32)
    __shared__ float part_sh[2][NB][G1];                 // 32 KB: half-dot partials

    const int tid  = threadIdx.x;
    const int b0   = blockIdx.x * NB;
    const int wid  = tid >> 5;
    const int lane = tid & 31;
    const int p    = tid & 127;   // gate-pair id: gates p and p+128
    const int kh   = tid >> 7;    // K-half (0: k 0..31, 1: k 32..63)

    // ---- weights: two gate half-rows, packed f32x2 (80 regs total) ----
    ull wa[16], wb[16];   // w_hh1[p, kh*32..+32), w_hh1[p+128, kh*32..+32)
    ull wxa[4], wxb[4];   // w_ih1[p, kh*8..+8),   w_ih1[p+128, kh*8..+8)
    {
        const ulonglong2* ra = (const ulonglong2*)(w_hh1 + p * H1 + kh * 32);
        const ulonglong2* rb = (const ulonglong2*)(w_hh1 + (p + 128) * H1 + kh * 32);
        #pragma unroll
        for (int m = 0; m < 8; m++) {
            ulonglong2 va = ra[m]; wa[2*m] = va.x; wa[2*m+1] = va.y;
            ulonglong2 vb = rb[m]; wb[2*m] = vb.x; wb[2*m+1] = vb.y;
        }
        const ulonglong2* ia = (const ulonglong2*)(w_ih1 + p * IN_DIM + kh * 8);
        const ulonglong2* ib = (const ulonglong2*)(w_ih1 + (p + 128) * IN_DIM + kh * 8);
        #pragma unroll
        for (int m = 0; m < 2; m++) {
            ulonglong2 va = ia[m]; wxa[2*m] = va.x; wxa[2*m+1] = va.y;
            ulonglong2 vb = ib[m]; wxb[2*m] = vb.x; wxb[2*m+1] = vb.y;
        }
    }
    // bias folded into the kh==0 partial
    const float ba = (kh == 0) ? (b_ih1[p] + b_hh1[p]) : 0.0f;
    const float bb = (kh == 0) ? (b_ih1[p + 128] + b_hh1[p + 128]) : 0.0f;

    // ---- layer-2 + FC per-warp setup: warp w -> batches 2w, 2w+1 ----
    const int q  = lane >> 3;
    const int ch = lane & 7;
    float w2[8];
    #pragma unroll
    for (int m = 0; m < 8; m++) w2[m] = w_ih2[q * H1 + ch * 8 + m];
    const float bias2 = b_ih2[q] + b_hh2[q];
    const float whh2  = w_hh2[q];
    const float fcw   = fc_w[0];
    const float fcb   = fc_b[0];

    // ---- states ----
    float c1[4];                 // 4 cells per thread: cell id = k*256 + tid
    #pragma unroll
    for (int k = 0; k < 4; k++) c1[k] = 0.0f;
    float c2[2] = {0.0f, 0.0f};  // layer-2 per-warp (2 batches)
    float h2[2] = {0.0f, 0.0f};
    #pragma unroll
    for (int k = 0; k < 4; k++) h_sh[k * 256 + tid] = 0.0f;

    const float* hb2a = h_sh + (wid * 2 + 0) * H1 + ch * 8;
    const float* hb2b = h_sh + (wid * 2 + 1) * H1 + ch * 8;
    float* outa = out + (b0 + wid * 2 + 0) * T_STEPS;
    float* outc = out + (b0 + wid * 2 + 1) * T_STEPS;

    // x staging: every thread owns (xnb = tid>>4, xi = tid&15)
    const float* xsrc = x + ((b0 + (tid >> 4)) * T_STEPS) * IN_DIM + (tid & 15);
    x_sh[tid] = xsrc[0];
    __syncthreads();

    for (int t = 0; t < T_STEPS; t++) {
        // ---- phase 1: prefetch x(t+1); half-dots for 16 batches; layer2(t-1) ----
        float xr = 0.0f;
        if (t + 1 < T_STEPS) xr = xsrc[(t + 1) * IN_DIM];

        #pragma unroll 4
        for (int nb = 0; nb < NB; nb++) {
            ull aa0 = 0, aa1 = 0, ab0 = 0, ab1 = 0;
            const ulonglong2* hv = (const ulonglong2*)(h_sh + nb * H1 + kh * 32);
            #pragma unroll
            for (int m = 0; m < 8; m++) {
                ulonglong2 v = hv[m];      // one load feeds BOTH gate half-dots
                aa0 = fma2(wa[2*m + 0], v.x, aa0);
                aa1 = fma2(wa[2*m + 1], v.y, aa1);
                ab0 = fma2(wb[2*m + 0], v.x, ab0);
                ab1 = fma2(wb[2*m + 1], v.y, ab1);
            }
            const ulonglong2* xv = (const ulonglong2*)(x_sh + nb * IN_DIM + kh * 8);
            #pragma unroll
            for (int m = 0; m < 2; m++) {
                ulonglong2 v = xv[m];
                aa0 = fma2(wxa[2*m + 0], v.x, aa0);
                aa1 = fma2(wxa[2*m + 1], v.y, aa1);
                ab0 = fma2(wxb[2*m + 0], v.x, ab0);
                ab1 = fma2(wxb[2*m + 1], v.y, ab1);
            }
            float2 fa0 = u2f(aa0), fa1 = u2f(aa1);
            float2 fb0 = u2f(ab0), fb1 = u2f(ab1);
            part_sh[kh][nb][p]       = (fa0.x + fa0.y) + (fa1.x + fa1.y) + ba;
            part_sh[kh][nb][p + 128] = (fb0.x + fb0.y) + (fb1.x + fb1.y) + bb;
        }

        // deferred layer-2 for t-1 (pure reader of h_sh = h1(t-1)); 2 batches/warp
        if (t > 0) {
            layer2_pair(hb2a, hb2b, w2, bias2, whh2, fcw, fcb,
                        h2[0], c2[0], h2[1], c2[1], outa + (t - 1), outc + (t - 1), lane);
        }
        __syncthreads();

        // ---- phase 2: combine halves, activate, update 4 cells; publish x ----
        #pragma unroll
        for (int k = 0; k < 4; k++) {
            const int cell = k * 256 + tid;          // 0..1023
            const int unb  = cell >> 6;              // batch 0..15
            const int uj   = cell & 63;              // hidden index
            float pi = part_sh[0][unb][uj]        + part_sh[1][unb][uj];
            float pf = part_sh[0][unb][64 + uj]   + part_sh[1][unb][64 + uj];
            float pg = part_sh[0][unb][128 + uj]  + part_sh[1][unb][128 + uj];
            float po = part_sh[0][unb][192 + uj]  + part_sh[1][unb][192 + uj];
            float gi = sigmoid_f(pi);
            float gf = sigmoid_f(pf);
            float gg = tanh_f(pg);
            float go = sigmoid_f(po);
            c1[k] = fmaf(gf, c1[k], gi * gg);
            h_sh[unb * H1 + uj] = go * tanh_f(c1[k]);
        }
        x_sh[tid] = xr;
        __syncthreads();   // h(t), x(t+1) published
    }

    // Tail: layer-2 + FC for the final timestep (h1(T-1))
    layer2_pair(hb2a, hb2b, w2, bias2, whh2, fcw, fcb,
                h2[0], c2[0], h2[1], c2[1],
                outa + (T_STEPS - 1), outc + (T_STEPS - 1), lane);
}

extern "C" void kernel_launch(void* const* d_in, const int* in_sizes, int n_in,
                              void* d_out, int out_size) {
    const int B = in_sizes[0] / (T_STEPS * IN_DIM);   // 4096
    lstm_fused_kernel<<<B / NB, THREADS>>>(
        (const float*)d_in[0],
        (const float*)d_in[1], (const float*)d_in[2],
        (const float*)d_in[3], (const float*)d_in[4],
        (const float*)d_in[5], (const float*)d_in[6],
        (const float*)d_in[7], (const float*)d_in[8],
        (const float*)d_in[9], (const float*)d_in[10],
        (float*)d_out);
}

// round 16
// speedup vs baseline: 1.5810x; 1.0563x over previous
#include <cuda_runtime.h>

// Fused 2-layer LSTM + FC decoder — gate-pair x K-half + balanced grid.
// x:[4096,256,16] -> LSTM(16->64) -> LSTM(64->1) -> FC(1->1) -> out:[4096,256,1]
//
// grid = 296 blocks (exactly 2 per SM on 148 SMs): 248 blocks x 14 batches +
// 48 blocks x 13 batches = 4096. 256 threads. Thread (p = tid&127, kh =
// tid>>7) owns gates {p, p+128} restricted to K-half kh (80 weight regs,
// packed f32x2). Per nb: 10 LDS.128 feed 40 fma2 -> 2 partials to smem.
// Phase 2 combines halves, activates (tanh.approx), updates c/h.
// Layer 2 (H=1)+FC: 2 batches/warp, pair-interleaved, deferred one step.

#define T_STEPS 256
#define IN_DIM  16
#define H1      64
#define G1      256   // 4*H1
#define NBMAX   14
#define THREADS 256

typedef unsigned long long ull;

__device__ __forceinline__ ull fma2(ull a, ull b, ull c) {
    ull d;
    asm("fma.rn.f32x2 %0, %1, %2, %3;" : "=l"(d) : "l"(a), "l"(b), "l"(c));
    return d;
}
__device__ __forceinline__ float2 u2f(ull v) {
    float2 r;
    asm("mov.b64 {%0, %1}, %2;" : "=f"(r.x), "=f"(r.y) : "l"(v));
    return r;
}

__device__ __forceinline__ float tanh_f(float x) {
    float y;
    asm("tanh.approx.f32 %0, %1;" : "=f"(y) : "f"(x));
    return y;
}
__device__ __forceinline__ float sigmoid_f(float x) {
    return fmaf(0.5f, tanh_f(0.5f * x), 0.5f);
}

// LSTM2 (H=1) + FC for TWO batch elements, one warp, chains interleaved.
// Stores predicated on va/vb (batch validity); compute is unconditional.
__device__ __forceinline__ void layer2_pair(const float* __restrict__ hb0,
                                            const float* __restrict__ hb1,
                                            const float w2[8], float bias2, float whh2,
                                            float fcw, float fcb,
                                            float& h2a, float& c2a,
                                            float& h2b, float& c2b,
                                            float* __restrict__ o0, float* __restrict__ o1,
                                            int lane, bool va, bool vb)
{
    float p0 = 0.0f, p1 = 0.0f;
    #pragma unroll
    for (int m = 0; m < 8; m++) {
        p0 = fmaf(w2[m], hb0[m], p0);
        p1 = fmaf(w2[m], hb1[m], p1);
    }
    p0 += __shfl_down_sync(0xffffffffu, p0, 4);
    p1 += __shfl_down_sync(0xffffffffu, p1, 4);
    p0 += __shfl_down_sync(0xffffffffu, p0, 2);
    p1 += __shfl_down_sync(0xffffffffu, p1, 2);
    p0 += __shfl_down_sync(0xffffffffu, p0, 1);
    p1 += __shfl_down_sync(0xffffffffu, p1, 1);
    float ga = fmaf(whh2, h2a, p0 + bias2);   // valid where (lane&7)==0
    float gb = fmaf(whh2, h2b, p1 + bias2);
    float gi0 = __shfl_sync(0xffffffffu, ga, 0),  gi1 = __shfl_sync(0xffffffffu, gb, 0);
    float gf0 = __shfl_sync(0xffffffffu, ga, 8),  gf1 = __shfl_sync(0xffffffffu, gb, 8);
    float gg0 = __shfl_sync(0xffffffffu, ga, 16), gg1 = __shfl_sync(0xffffffffu, gb, 16);
    float go0 = __shfl_sync(0xffffffffu, ga, 24), go1 = __shfl_sync(0xffffffffu, gb, 24);
    float i0 = sigmoid_f(gi0), i1 = sigmoid_f(gi1);
    float f0 = sigmoid_f(gf0), f1 = sigmoid_f(gf1);
    float tg0 = tanh_f(gg0),   tg1 = tanh_f(gg1);
    float o0v = sigmoid_f(go0), o1v = sigmoid_f(go1);
    c2a = fmaf(f0, c2a, i0 * tg0);
    c2b = fmaf(f1, c2b, i1 * tg1);
    h2a = o0v * tanh_f(c2a);
    h2b = o1v * tanh_f(c2b);
    if (lane == 0) {
        if (va) *o0 = fmaf(h2a, fcw, fcb);
        if (vb) *o1 = fmaf(h2b, fcw, fcb);
    }
}

__global__ __launch_bounds__(THREADS, 2)
void lstm_fused_kernel(const float* __restrict__ x,
                       const float* __restrict__ w_ih1, const float* __restrict__ w_hh1,
                       const float* __restrict__ b_ih1, const float* __restrict__ b_hh1,
                       const float* __restrict__ w_ih2, const float* __restrict__ w_hh2,
                       const float* __restrict__ b_ih2, const float* __restrict__ b_hh2,
                       const float* __restrict__ fc_w, const float* __restrict__ fc_b,
                       float* __restrict__ out)
{
    __shared__ __align__(16) float x_sh[NBMAX * IN_DIM];   // staged x(t)
    __shared__ __align__(16) float h_sh[NBMAX * H1];       // layer-1 hidden (fp32)
    __shared__ float part_sh[2][NBMAX][G1];                 // half-dot partials

    const int tid  = threadIdx.x;
    const int bid  = blockIdx.x;
    // 248 blocks of 14 batches, then 48 blocks of 13: 248*14 + 48*13 = 4096
    const int nbv  = (bid < 248) ? 14 : 13;
    const int b0   = (bid < 248) ? bid * 14 : 3472 + (bid - 248) * 13;
    const int wid  = tid >> 5;
    const int lane = tid & 31;
    const int p    = tid & 127;   // gate-pair id: gates p and p+128
    const int kh   = tid >> 7;    // K-half (0: k 0..31, 1: k 32..63)

    // ---- weights: two gate half-rows, packed f32x2 (80 regs total) ----
    ull wa[16], wb[16];   // w_hh1[p, kh*32..+32), w_hh1[p+128, kh*32..+32)
    ull wxa[4], wxb[4];   // w_ih1[p, kh*8..+8),   w_ih1[p+128, kh*8..+8)
    {
        const ulonglong2* ra = (const ulonglong2*)(w_hh1 + p * H1 + kh * 32);
        const ulonglong2* rb = (const ulonglong2*)(w_hh1 + (p + 128) * H1 + kh * 32);
        #pragma unroll
        for (int m = 0; m < 8; m++) {
            ulonglong2 va = ra[m]; wa[2*m] = va.x; wa[2*m+1] = va.y;
            ulonglong2 vb = rb[m]; wb[2*m] = vb.x; wb[2*m+1] = vb.y;
        }
        const ulonglong2* ia = (const ulonglong2*)(w_ih1 + p * IN_DIM + kh * 8);
        const ulonglong2* ib = (const ulonglong2*)(w_ih1 + (p + 128) * IN_DIM + kh * 8);
        #pragma unroll
        for (int m = 0; m < 2; m++) {
            ulonglong2 va = ia[m]; wxa[2*m] = va.x; wxa[2*m+1] = va.y;
            ulonglong2 vb = ib[m]; wxb[2*m] = vb.x; wxb[2*m+1] = vb.y;
        }
    }
    // bias folded into the kh==0 partial
    const float ba = (kh == 0) ? (b_ih1[p] + b_hh1[p]) : 0.0f;
    const float bb = (kh == 0) ? (b_ih1[p + 128] + b_hh1[p + 128]) : 0.0f;

    // ---- layer-2 + FC per-warp setup: warp w -> batches 2w, 2w+1 ----
    const int q  = lane >> 3;
    const int ch = lane & 7;
    float w2[8];
    #pragma unroll
    for (int m = 0; m < 8; m++) w2[m] = w_ih2[q * H1 + ch * 8 + m];
    const float bias2 = b_ih2[q] + b_hh2[q];
    const float whh2  = w_hh2[q];
    const float fcw   = fc_w[0];
    const float fcb   = fc_b[0];

    // ---- states ----
    float c1[4];
    #pragma unroll
    for (int k = 0; k < 4; k++) c1[k] = 0.0f;
    float c2[2] = {0.0f, 0.0f};
    float h2[2] = {0.0f, 0.0f};
    #pragma unroll
    for (int k = 0; k < 4; k++) {
        int idx = k * 256 + tid;
        if (idx < NBMAX * H1) h_sh[idx] = 0.0f;
    }

    // layer-2 batch validity + clamped pointers (stay in h_sh bounds)
    const bool l2va = (2 * wid)     < nbv;
    const bool l2vb = (2 * wid + 1) < nbv;
    const int  bA = l2va ? 2 * wid     : 0;
    const int  bB = l2vb ? 2 * wid + 1 : 0;
    const float* hb2a = h_sh + bA * H1 + ch * 8;
    const float* hb2b = h_sh + bB * H1 + ch * 8;
    float* outa = out + (b0 + bA) * T_STEPS;
    float* outc = out + (b0 + bB) * T_STEPS;

    // x staging: thread stages (xnb = tid>>4, xi = tid&15) if xnb < nbv
    const int  xnb   = tid >> 4;
    const bool xduty = (xnb < nbv);
    const float* xsrc = x + ((b0 + (xduty ? xnb : 0)) * T_STEPS) * IN_DIM + (tid & 15);
    if (xduty) x_sh[tid] = xsrc[0];
    __syncthreads();

    for (int t = 0; t < T_STEPS; t++) {
        // ---- phase 1: prefetch x(t+1); half-dots for nbv batches; layer2(t-1) ----
        float xr = 0.0f;
        if (xduty && t + 1 < T_STEPS) xr = xsrc[(t + 1) * IN_DIM];

        #pragma unroll 2
        for (int nb = 0; nb < nbv; nb++) {
            ull aa0 = 0, aa1 = 0, ab0 = 0, ab1 = 0;
            const ulonglong2* hv = (const ulonglong2*)(h_sh + nb * H1 + kh * 32);
            #pragma unroll
            for (int m = 0; m < 8; m++) {
                ulonglong2 v = hv[m];      // one load feeds BOTH gate half-dots
                aa0 = fma2(wa[2*m + 0], v.x, aa0);
                aa1 = fma2(wa[2*m + 1], v.y, aa1);
                ab0 = fma2(wb[2*m + 0], v.x, ab0);
                ab1 = fma2(wb[2*m + 1], v.y, ab1);
            }
            const ulonglong2* xv = (const ulonglong2*)(x_sh + nb * IN_DIM + kh * 8);
            #pragma unroll
            for (int m = 0; m < 2; m++) {
                ulonglong2 v = xv[m];
                aa0 = fma2(wxa[2*m + 0], v.x, aa0);
                aa1 = fma2(wxa[2*m + 1], v.y, aa1);
                ab0 = fma2(wxb[2*m + 0], v.x, ab0);
                ab1 = fma2(wxb[2*m + 1], v.y, ab1);
            }
            float2 fa0 = u2f(aa0), fa1 = u2f(aa1);
            float2 fb0 = u2f(ab0), fb1 = u2f(ab1);
            part_sh[kh][nb][p]       = (fa0.x + fa0.y) + (fa1.x + fa1.y) + ba;
            part_sh[kh][nb][p + 128] = (fb0.x + fb0.y) + (fb1.x + fb1.y) + bb;
        }

        // deferred layer-2 for t-1 (pure reader of h_sh = h1(t-1)); 2 batches/warp
        if (t > 0) {
            layer2_pair(hb2a, hb2b, w2, bias2, whh2, fcw, fcb,
                        h2[0], c2[0], h2[1], c2[1],
                        outa + (t - 1), outc + (t - 1), lane, l2va, l2vb);
        }
        __syncthreads();

        // ---- phase 2: combine halves, activate, update cells; publish x ----
        const int ncell = nbv * H1;
        #pragma unroll
        for (int k = 0; k < 4; k++) {
            const int cell = k * 256 + tid;
            if (cell < ncell) {
                const int unb = cell >> 6;           // batch
                const int uj  = cell & 63;           // hidden index
                float pi = part_sh[0][unb][uj]        + part_sh[1][unb][uj];
                float pf = part_sh[0][unb][64 + uj]   + part_sh[1][unb][64 + uj];
                float pg = part_sh[0][unb][128 + uj]  + part_sh[1][unb][128 + uj];
                float po = part_sh[0][unb][192 + uj]  + part_sh[1][unb][192 + uj];
                float gi = sigmoid_f(pi);
                float gf = sigmoid_f(pf);
                float gg = tanh_f(pg);
                float go = sigmoid_f(po);
                c1[k] = fmaf(gf, c1[k], gi * gg);
                h_sh[unb * H1 + uj] = go * tanh_f(c1[k]);
            }
        }
        if (xduty) x_sh[tid] = xr;
        __syncthreads();   // h(t), x(t+1) published
    }

    // Tail: layer-2 + FC for the final timestep (h1(T-1))
    layer2_pair(hb2a, hb2b, w2, bias2, whh2, fcw, fcb,
                h2[0], c2[0], h2[1], c2[1],
                outa + (T_STEPS - 1), outc + (T_STEPS - 1), lane, l2va, l2vb);
}

extern "C" void kernel_launch(void* const* d_in, const int* in_sizes, int n_in,
                              void* d_out, int out_size) {
    // 296 blocks = 2 per SM on 148 SMs; 248x14 + 48x13 = 4096 batches
    lstm_fused_kernel<<<296, THREADS>>>(
        (const float*)d_in[0],
        (const float*)d_in[1], (const float*)d_in[2],
        (const float*)d_in[3], (const float*)d_in[4],
        (const float*)d_in[5], (const float*)d_in[6],
        (const float*)d_in[7], (const float*)d_in[8],
        (const float*)d_in[9], (const float*)d_in[10],
        (float*)d_out);
}